// round 15
// baseline (speedup 1.0000x reference)
#include <cuda_runtime.h>
#include <cuda_bf16.h>
#include <math.h>
#include <stdint.h>

// Problem constants (fixed for this dataset)
#define NN 20000
#define EE 320000
#define SED 768
#define F1 512      // H*HID = 4*128
#define H1H 4
#define HID 128
#define F2 128

// ---------------- scratch (static device globals; no allocation) -------------
__device__ float g_c1[F1];
__device__ float g_h1[(size_t)NN * F1];
__device__ unsigned g_out1_tf[(size_t)NN * F1];   // layer1 output pre-converted to tf32 bits
__device__ float g_h2[(size_t)NN * F2];
__device__ unsigned g_x_tf[(size_t)NN * SED];     // x pre-converted to tf32 bits
__device__ unsigned g_w1_tf[(size_t)SED * F1];    // W1[:768] tf32 bits
__device__ unsigned g_w2_tf[(size_t)F1 * F2];     // W2 tf32 bits
__device__ float g_es1[NN * H1H];
__device__ float g_ed1[NN * H1H];
__device__ float g_es2[NN];
__device__ float g_ed2[NN];
__device__ int   g_deg[NN];
__device__ int   g_off[NN + 1];
__device__ int   g_cur[NN];
__device__ int   g_perm[EE];

// ---------------- helpers ---------------------------------------------------
__device__ __forceinline__ float lrelu(float v) { return v >= 0.f ? v : 0.2f * v; }

__device__ __forceinline__ unsigned f2tf32(float f) {
    unsigned u;
    asm("cvt.rna.tf32.f32 %0, %1;\n" : "=r"(u) : "f"(f));
    return u;
}

// ---------------- fp32 -> tf32 bit conversion (vectorized) -------------------
__global__ void cvt_tf32_kernel(const float* __restrict__ src,
                                unsigned* __restrict__ dst, int n4) {
    int i = blockIdx.x * blockDim.x + threadIdx.x;
    if (i < n4) {
        float4 v = *(const float4*)(src + (size_t)i * 4);
        uint4 u;
        u.x = f2tf32(v.x); u.y = f2tf32(v.y);
        u.z = f2tf32(v.z); u.w = f2tf32(v.w);
        *(uint4*)(dst + (size_t)i * 4) = u;
    }
}

// ---------------- c1 = sent @ W1[768:, :] ------------------------------------
__global__ void zero_c1_kernel() { g_c1[threadIdx.x] = 0.f; }
__global__ void c1_partial_kernel(const float* __restrict__ sent,
                                  const float* __restrict__ W1) {
    int j = threadIdx.x;
    float acc = 0.f;
    #pragma unroll 8
    for (int k = 0; k < 64; k++) {
        int kk = blockIdx.x * 64 + k;
        acc += sent[kk] * W1[(size_t)(SED + kk) * F1 + j];
    }
    atomicAdd(&g_c1[j], acc);
}

// ---------------- tf32 tensor-core GEMM, double-buffered, pre-converted ------
// C[M,N] = A[M,K] @ B[K,N] (+bias[N]); A,B are tf32 bit patterns (unsigned).
// Optional fused attention logits (esOut != null).
// BM=128, BN=128, BK=16. 256 threads = 8 warps in 2(M) x 4(N); each warp 64x32.
#define GBM 128
#define GBN 128
#define GBK 16
#define SSTR 136

__global__ __launch_bounds__(256, 2) void tf32_gemm_kernel(
    int M, int N, int K,
    const unsigned* __restrict__ A, const unsigned* __restrict__ B,
    const float* __restrict__ bias, float* __restrict__ C,
    const float* __restrict__ aSrc, const float* __restrict__ aDst,
    float* __restrict__ esOut, float* __restrict__ edOut, int esStride)
{
    __shared__ unsigned As[2][GBK][SSTR];
    __shared__ unsigned Bs[2][GBK][SSTR];
    __shared__ float sEs[GBM], sEd[GBM];

    const int tid  = threadIdx.x;
    const int lane = tid & 31;
    const int wid  = tid >> 5;

    const int mBase = blockIdx.y * GBM;
    const int nBase = blockIdx.x * GBN;

    const int wm = (wid >> 2) * 64;
    const int wn = (wid & 3) * 32;

    const int aM  = tid >> 2;
    const int aK4 = (tid & 3) * 4;
    const int bK  = tid >> 5;
    const int bN4 = (tid & 31) * 4;

    const bool aOk0 = (mBase + aM) < M;
    const bool aOk1 = (mBase + aM + 64) < M;

    if (tid < GBM) { sEs[tid] = 0.f; sEd[tid] = 0.f; }

    float acc[4][4][4];
    #pragma unroll
    for (int mt = 0; mt < 4; mt++)
        #pragma unroll
        for (int nt = 0; nt < 4; nt++)
            #pragma unroll
            for (int r = 0; r < 4; r++) acc[mt][nt][r] = 0.f;

    const int NT = K / GBK;
    const uint4 z4 = make_uint4(0u, 0u, 0u, 0u);
    uint4 pa[2], pb[2];
    pa[0] = aOk0 ? *(const uint4*)(A + (size_t)(mBase + aM) * K + aK4) : z4;
    pa[1] = aOk1 ? *(const uint4*)(A + (size_t)(mBase + aM + 64) * K + aK4) : z4;
    pb[0] = *(const uint4*)(B + (size_t)bK * N + nBase + bN4);
    pb[1] = *(const uint4*)(B + (size_t)(bK + 8) * N + nBase + bN4);

    As[0][aK4 + 0][aM] = pa[0].x;
    As[0][aK4 + 1][aM] = pa[0].y;
    As[0][aK4 + 2][aM] = pa[0].z;
    As[0][aK4 + 3][aM] = pa[0].w;
    As[0][aK4 + 0][aM + 64] = pa[1].x;
    As[0][aK4 + 1][aM + 64] = pa[1].y;
    As[0][aK4 + 2][aM + 64] = pa[1].z;
    As[0][aK4 + 3][aM + 64] = pa[1].w;
    *(uint4*)&Bs[0][bK][bN4] = pb[0];
    *(uint4*)&Bs[0][bK + 8][bN4] = pb[1];
    __syncthreads();

    for (int t = 0; t < NT; t++) {
        const int cur = t & 1, nxt = cur ^ 1;
        const bool more = (t + 1) < NT;
        if (more) {
            int k0 = (t + 1) * GBK;
            pa[0] = aOk0 ? *(const uint4*)(A + (size_t)(mBase + aM) * K + k0 + aK4) : z4;
            pa[1] = aOk1 ? *(const uint4*)(A + (size_t)(mBase + aM + 64) * K + k0 + aK4) : z4;
            pb[0] = *(const uint4*)(B + (size_t)(k0 + bK) * N + nBase + bN4);
            pb[1] = *(const uint4*)(B + (size_t)(k0 + bK + 8) * N + nBase + bN4);
        }
        #pragma unroll
        for (int kk = 0; kk < GBK; kk += 8) {
            unsigned af[4][4];
            #pragma unroll
            for (int mt = 0; mt < 4; mt++) {
                int r0 = wm + mt * 16 + (lane >> 2);
                int c0 = kk + (lane & 3);
                af[mt][0] = As[cur][c0][r0];
                af[mt][1] = As[cur][c0][r0 + 8];
                af[mt][2] = As[cur][c0 + 4][r0];
                af[mt][3] = As[cur][c0 + 4][r0 + 8];
            }
            unsigned bf[4][2];
            #pragma unroll
            for (int nt = 0; nt < 4; nt++) {
                int cn = wn + nt * 8 + (lane >> 2);
                int rk = kk + (lane & 3);
                bf[nt][0] = Bs[cur][rk][cn];
                bf[nt][1] = Bs[cur][rk + 4][cn];
            }
            #pragma unroll
            for (int mt = 0; mt < 4; mt++)
                #pragma unroll
                for (int nt = 0; nt < 4; nt++) {
                    asm volatile(
                        "mma.sync.aligned.m16n8k8.row.col.f32.tf32.tf32.f32 "
                        "{%0,%1,%2,%3}, {%4,%5,%6,%7}, {%8,%9}, {%0,%1,%2,%3};\n"
                        : "+f"(acc[mt][nt][0]), "+f"(acc[mt][nt][1]),
                          "+f"(acc[mt][nt][2]), "+f"(acc[mt][nt][3])
                        : "r"(af[mt][0]), "r"(af[mt][1]), "r"(af[mt][2]), "r"(af[mt][3]),
                          "r"(bf[nt][0]), "r"(bf[nt][1]));
                }
        }
        if (more) {
            As[nxt][aK4 + 0][aM] = pa[0].x;
            As[nxt][aK4 + 1][aM] = pa[0].y;
            As[nxt][aK4 + 2][aM] = pa[0].z;
            As[nxt][aK4 + 3][aM] = pa[0].w;
            As[nxt][aK4 + 0][aM + 64] = pa[1].x;
            As[nxt][aK4 + 1][aM + 64] = pa[1].y;
            As[nxt][aK4 + 2][aM + 64] = pa[1].z;
            As[nxt][aK4 + 3][aM + 64] = pa[1].w;
            *(uint4*)&Bs[nxt][bK][bN4] = pb[0];
            *(uint4*)&Bs[nxt][bK + 8][bN4] = pb[1];
        }
        __syncthreads();
    }

    // epilogue: bias + store + optional fused es/ed dot products
    #pragma unroll
    for (int mt = 0; mt < 4; mt++) {
        int rl0 = wm + mt * 16 + (lane >> 2);
        int rl1 = rl0 + 8;
        int r0 = mBase + rl0;
        int r1 = mBase + rl1;
        float e0 = 0.f, e1 = 0.f, d0 = 0.f, d1 = 0.f;
        #pragma unroll
        for (int nt = 0; nt < 4; nt++) {
            int c = nBase + wn + nt * 8 + 2 * (lane & 3);
            float bx = 0.f, by = 0.f;
            if (bias) { bx = bias[c]; by = bias[c + 1]; }
            float v00 = acc[mt][nt][0] + bx, v01 = acc[mt][nt][1] + by;
            float v10 = acc[mt][nt][2] + bx, v11 = acc[mt][nt][3] + by;
            if (r0 < M) *(float2*)(C + (size_t)r0 * N + c) = make_float2(v00, v01);
            if (r1 < M) *(float2*)(C + (size_t)r1 * N + c) = make_float2(v10, v11);
            if (esOut) {
                float as0 = aSrc[c], as1 = aSrc[c + 1];
                float ad0 = aDst[c], ad1 = aDst[c + 1];
                e0 += v00 * as0 + v01 * as1;
                e1 += v10 * as0 + v11 * as1;
                d0 += v00 * ad0 + v01 * ad1;
                d1 += v10 * ad0 + v11 * ad1;
            }
        }
        if (esOut) {
            e0 += __shfl_xor_sync(0xffffffffu, e0, 1);
            e0 += __shfl_xor_sync(0xffffffffu, e0, 2);
            e1 += __shfl_xor_sync(0xffffffffu, e1, 1);
            e1 += __shfl_xor_sync(0xffffffffu, e1, 2);
            d0 += __shfl_xor_sync(0xffffffffu, d0, 1);
            d0 += __shfl_xor_sync(0xffffffffu, d0, 2);
            d1 += __shfl_xor_sync(0xffffffffu, d1, 1);
            d1 += __shfl_xor_sync(0xffffffffu, d1, 2);
            if ((lane & 3) == 0) {
                atomicAdd(&sEs[rl0], e0);
                atomicAdd(&sEs[rl1], e1);
                atomicAdd(&sEd[rl0], d0);
                atomicAdd(&sEd[rl1], d1);
            }
        }
    }
    if (esOut) {
        __syncthreads();
        if (tid < GBM) {
            int gRow = mBase + tid;
            if (gRow < M) {
                int head = nBase >> 7;          // BN == head width (128)
                esOut[gRow * esStride + head] = sEs[tid];
                edOut[gRow * esStride + head] = sEd[tid];
            }
        }
    }
}

// ---------------- CSR build ---------------------------------------------------
__global__ void zero_deg_kernel(int N) {
    int i = blockIdx.x * blockDim.x + threadIdx.x;
    if (i < N) g_deg[i] = 0;
}
__global__ void hist_kernel(const int* __restrict__ dst, int E) {
    int e = blockIdx.x * blockDim.x + threadIdx.x;
    if (e < E) atomicAdd(&g_deg[dst[e]], 1);
}
__global__ void scan_kernel(int N) {
    __shared__ int wsum[32];
    __shared__ int carry;
    int tid = threadIdx.x, lane = tid & 31, w = tid >> 5;
    if (tid == 0) { carry = 0; g_off[0] = 0; }
    __syncthreads();
    for (int base = 0; base < N; base += 1024) {
        int i = base + tid;
        int v = (i < N) ? g_deg[i] : 0;
        int x = v;
        #pragma unroll
        for (int o = 1; o < 32; o <<= 1) {
            int t = __shfl_up_sync(0xffffffffu, x, o);
            if (lane >= o) x += t;
        }
        if (lane == 31) wsum[w] = x;
        __syncthreads();
        if (w == 0) {
            int y = wsum[lane];
            #pragma unroll
            for (int o = 1; o < 32; o <<= 1) {
                int t = __shfl_up_sync(0xffffffffu, y, o);
                if (lane >= o) y += t;
            }
            wsum[lane] = y;
        }
        __syncthreads();
        int incl = x + (w > 0 ? wsum[w - 1] : 0) + carry;
        if (i < N) {
            g_off[i + 1] = incl;
            g_cur[i] = incl - v;
        }
        __syncthreads();
        if (tid == 1023) carry = incl;
        __syncthreads();
    }
}
__global__ void scatter_kernel(const int* __restrict__ dst, int E) {
    int e = blockIdx.x * blockDim.x + threadIdx.x;
    if (e < E) {
        int d = dst[e];
        int p = atomicAdd(&g_cur[d], 1);
        g_perm[p] = e;
    }
}

// ---------------- layer-1 softmax + aggregation + bias + ELU -----------------
// writes out1 pre-converted to tf32 bits (identical cvt GEMM2 would apply)
__global__ __launch_bounds__(128) void agg1_kernel(
    const int* __restrict__ srcArr, const float* __restrict__ b1)
{
    int dst = blockIdx.x, tid = threadIdx.x;
    int lane = tid & 31, w = tid >> 5;
    __shared__ float m_s[4], inv_s[4], ed_s[4];
    __shared__ float w_s[256];
    __shared__ int   src_s[64];

    int beg = g_off[dst];
    int deg = g_off[dst + 1] - beg;
    if (tid < 4) ed_s[tid] = g_ed1[dst * H1H + tid];
    __syncthreads();

    float edh = ed_s[w];
    float m = -1e30f;
    for (int i = lane; i < deg; i += 32) {
        int s = srcArr[g_perm[beg + i]];
        float v = lrelu(g_es1[s * H1H + w] + edh);
        m = fmaxf(m, v);
    }
    #pragma unroll
    for (int o = 16; o; o >>= 1) m = fmaxf(m, __shfl_xor_sync(0xffffffffu, m, o));
    float sum = 0.f;
    for (int i = lane; i < deg; i += 32) {
        int s = srcArr[g_perm[beg + i]];
        float v = lrelu(g_es1[s * H1H + w] + edh);
        sum += expf(v - m);
    }
    #pragma unroll
    for (int o = 16; o; o >>= 1) sum += __shfl_xor_sync(0xffffffffu, sum, o);
    if (lane == 0) { m_s[w] = m; inv_s[w] = 1.f / (sum + 1e-16f); }
    __syncthreads();

    const int c4 = lane * 4;
    float4 acc = make_float4(0.f, 0.f, 0.f, 0.f);
    for (int base = 0; base < deg; base += 64) {
        int cnt = min(64, deg - base);
        if (tid < cnt) src_s[tid] = srcArr[g_perm[beg + base + tid]];
        __syncthreads();
        for (int idx = tid; idx < cnt * 4; idx += 128) {
            int eidx = idx >> 2, h = idx & 3;
            int s = src_s[eidx];
            float v = lrelu(g_es1[s * H1H + h] + ed_s[h]);
            w_s[idx] = expf(v - m_s[h]) * inv_s[h];
        }
        __syncthreads();
        #pragma unroll 4
        for (int eidx = 0; eidx < cnt; eidx++) {
            const float4 v = *(const float4*)(g_h1 + (size_t)src_s[eidx] * F1 + w * HID + c4);
            float wt = w_s[eidx * 4 + w];
            acc.x += wt * v.x; acc.y += wt * v.y;
            acc.z += wt * v.z; acc.w += wt * v.w;
        }
        __syncthreads();
    }

    int cg = w * HID + c4;
    float4 bv = *(const float4*)(b1 + cg);
    float o0 = acc.x + bv.x, o1 = acc.y + bv.y, o2 = acc.z + bv.z, o3 = acc.w + bv.w;
    o0 = o0 > 0.f ? o0 : expm1f(o0);
    o1 = o1 > 0.f ? o1 : expm1f(o1);
    o2 = o2 > 0.f ? o2 : expm1f(o2);
    o3 = o3 > 0.f ? o3 : expm1f(o3);
    uint4 u;
    u.x = f2tf32(o0); u.y = f2tf32(o1); u.z = f2tf32(o2); u.w = f2tf32(o3);
    *(uint4*)(g_out1_tf + (size_t)dst * F1 + cg) = u;
}

// ---------------- layer-2 softmax + aggregation + bias -----------------------
__global__ __launch_bounds__(128) void agg2_kernel(
    const int* __restrict__ srcArr, const float* __restrict__ b2,
    float* __restrict__ out)
{
    int dst = blockIdx.x, tid = threadIdx.x;
    int lane = tid & 31, w = tid >> 5;
    __shared__ float red[4];
    __shared__ float w_s[128];
    __shared__ int   src_s[128];
    __shared__ float4 red4[4][32];

    int beg = g_off[dst];
    int deg = g_off[dst + 1] - beg;
    float edv = g_ed2[dst];

    float m = -1e30f;
    for (int i = tid; i < deg; i += 128) {
        int s = srcArr[g_perm[beg + i]];
        m = fmaxf(m, lrelu(g_es2[s] + edv));
    }
    #pragma unroll
    for (int o = 16; o; o >>= 1) m = fmaxf(m, __shfl_xor_sync(0xffffffffu, m, o));
    if (lane == 0) red[w] = m;
    __syncthreads();
    m = fmaxf(fmaxf(red[0], red[1]), fmaxf(red[2], red[3]));
    __syncthreads();

    float sum = 0.f;
    for (int i = tid; i < deg; i += 128) {
        int s = srcArr[g_perm[beg + i]];
        sum += expf(lrelu(g_es2[s] + edv) - m);
    }
    #pragma unroll
    for (int o = 16; o; o >>= 1) sum += __shfl_xor_sync(0xffffffffu, sum, o);
    if (lane == 0) red[w] = sum;
    __syncthreads();
    sum = red[0] + red[1] + red[2] + red[3];
    float inv = 1.f / (sum + 1e-16f);

    float4 acc = make_float4(0.f, 0.f, 0.f, 0.f);
    for (int base = 0; base < deg; base += 128) {
        int cnt = min(128, deg - base);
        __syncthreads();
        if (tid < cnt) {
            int s = srcArr[g_perm[beg + base + tid]];
            src_s[tid] = s;
            w_s[tid] = expf(lrelu(g_es2[s] + edv) - m) * inv;
        }
        __syncthreads();
        for (int e = w; e < cnt; e += 4) {
            int s = src_s[e];
            float wt = w_s[e];
            const float4 v = *(const float4*)(g_h2 + (size_t)s * F2 + lane * 4);
            acc.x += wt * v.x; acc.y += wt * v.y;
            acc.z += wt * v.z; acc.w += wt * v.w;
        }
    }
    red4[w][lane] = acc;
    __syncthreads();
    if (w == 0) {
        float4 a0 = red4[0][lane], a1 = red4[1][lane];
        float4 a2 = red4[2][lane], a3 = red4[3][lane];
        float4 bv = *(const float4*)(b2 + lane * 4);
        float4 r;
        r.x = a0.x + a1.x + a2.x + a3.x + bv.x;
        r.y = a0.y + a1.y + a2.y + a3.y + bv.y;
        r.z = a0.z + a1.z + a2.z + a3.z + bv.z;
        r.w = a0.w + a1.w + a2.w + a3.w + bv.w;
        *(float4*)(out + (size_t)dst * F2 + lane * 4) = r;
    }
}

// ---------------- launch ------------------------------------------------------
extern "C" void kernel_launch(void* const* d_in, const int* in_sizes, int n_in,
                              void* d_out, int out_size) {
    const float* x    = (const float*)d_in[0];
    const int*   ei   = (const int*)d_in[1];
    const float* sent = (const float*)d_in[2];
    const float* W1   = (const float*)d_in[3];
    const float* a1s  = (const float*)d_in[4];
    const float* a1d  = (const float*)d_in[5];
    const float* b1   = (const float*)d_in[6];
    const float* W2   = (const float*)d_in[7];
    const float* a2s  = (const float*)d_in[8];
    const float* a2d  = (const float*)d_in[9];
    const float* b2   = (const float*)d_in[10];
    float* out = (float*)d_out;

    const int N = in_sizes[0] / SED;   // 20000
    const int E = in_sizes[1] / 2;     // 320000
    const int* srcArr = ei;
    const int* dstArr = ei + E;

    float* p_c1; float* p_h1; float* p_h2;
    unsigned* p_x_tf; unsigned* p_w1_tf; unsigned* p_w2_tf; unsigned* p_out1_tf;
    float* p_es1; float* p_ed1; float* p_es2; float* p_ed2;
    cudaGetSymbolAddress((void**)&p_c1,      g_c1);
    cudaGetSymbolAddress((void**)&p_h1,      g_h1);
    cudaGetSymbolAddress((void**)&p_h2,      g_h2);
    cudaGetSymbolAddress((void**)&p_x_tf,    g_x_tf);
    cudaGetSymbolAddress((void**)&p_w1_tf,   g_w1_tf);
    cudaGetSymbolAddress((void**)&p_w2_tf,   g_w2_tf);
    cudaGetSymbolAddress((void**)&p_out1_tf, g_out1_tf);
    cudaGetSymbolAddress((void**)&p_es1,     g_es1);
    cudaGetSymbolAddress((void**)&p_ed1,     g_ed1);
    cudaGetSymbolAddress((void**)&p_es2,     g_es2);
    cudaGetSymbolAddress((void**)&p_ed2,     g_ed2);

    static cudaStream_t s_side = nullptr;
    static cudaEvent_t  s_evFork = nullptr, s_evJoin = nullptr;
    static bool s_ok = false;
    if (!s_side) {
        s_ok = (cudaStreamCreateWithFlags(&s_side, cudaStreamNonBlocking) == cudaSuccess) &&
               (cudaEventCreateWithFlags(&s_evFork, cudaEventDisableTiming) == cudaSuccess) &&
               (cudaEventCreateWithFlags(&s_evJoin, cudaEventDisableTiming) == cudaSuccess);
    }

    cudaStream_t csr = s_ok ? s_side : (cudaStream_t)0;
    if (s_ok) {
        cudaEventRecord(s_evFork, 0);
        cudaStreamWaitEvent(s_side, s_evFork, 0);
    }

    // side chain start: degree zero (tiny)
    zero_deg_kernel<<<(N + 255) / 256, 256, 0, csr>>>(N);

    // main chain: operand pre-conversion + rank-1 sentence vector
    cvt_tf32_kernel<<<(SED * F1 / 4 + 255) / 256, 256>>>(W1, p_w1_tf, SED * F1 / 4);
    cvt_tf32_kernel<<<(F1 * F2 / 4 + 255) / 256, 256>>>(W2, p_w2_tf, F1 * F2 / 4);
    cvt_tf32_kernel<<<(N * SED / 4 + 255) / 256, 256>>>(x, p_x_tf, N * SED / 4);
    zero_c1_kernel<<<1, F1>>>();
    c1_partial_kernel<<<12, F1>>>(sent, W1);

    // GEMM1 = x @ W1[:768] + c1, fused es1/ed1
    {
        dim3 grid(F1 / GBN, (N + GBM - 1) / GBM);
        tf32_gemm_kernel<<<grid, 256>>>(N, F1, SED, p_x_tf, p_w1_tf, p_c1, p_h1,
                                        a1s, a1d, p_es1, p_ed1, H1H);
    }

    // remaining CSR chain on side stream (overlaps conversions + GEMM1)
    hist_kernel<<<(E + 255) / 256, 256, 0, csr>>>(dstArr, E);
    scan_kernel<<<1, 1024, 0, csr>>>(N);
    scatter_kernel<<<(E + 255) / 256, 256, 0, csr>>>(dstArr, E);
    if (s_ok) cudaEventRecord(s_evJoin, s_side);
    if (s_ok) cudaStreamWaitEvent((cudaStream_t)0, s_evJoin, 0);

    // layer-1 attention aggregate + bias + ELU (writes tf32 out1)
    agg1_kernel<<<N, 128>>>(srcArr, b1);

    // GEMM2 = out1 @ W2, fused es2/ed2
    {
        dim3 grid(F2 / GBN, (N + GBM - 1) / GBM);
        tf32_gemm_kernel<<<grid, 256>>>(N, F2, F1, p_out1_tf, p_w2_tf, nullptr, p_h2,
                                        a2s, a2d, p_es2, p_ed2, 1);
    }

    // layer-2 attention aggregate + bias -> output
    agg2_kernel<<<N, 128>>>(srcArr, b2, out);
}